// round 6
// baseline (speedup 1.0000x reference)
#include <cuda_runtime.h>
#include <cuda_bf16.h>

// Problem shapes (fixed by the dataset)
#define BB   8
#define TT   2048
#define DD   1024
#define HH   8
#define SS   128
#define DH   128     // D / H
#define MAXW 32      // max span width
#define NK   (DD/4) // 256 float4 per row

__global__ __launch_bounds__(256)
void pooler_kernel(const float* __restrict__ features,
                   const int*   __restrict__ begins32,
                   const int*   __restrict__ ends32,
                   const float* __restrict__ key_w,
                   const float* __restrict__ key_b,
                   float*       __restrict__ out)
{
    __shared__ float4 sw4[HH * NK];   // key_w, 32 KB
    __shared__ float  sb[HH];
    __shared__ float  slog[MAXW][HH]; // logits -> softmax weights
    __shared__ int    sspan[2];

    const int tid  = threadIdx.x;
    const int wid  = tid >> 5;
    const int lane = tid & 31;
    const int blk  = blockIdx.x;     // blk = b*S + s
    const int b    = blk >> 7;       // / SS

    // ---- stage key_w / key_b into shared (L2-served, broadcast across blocks)
    const float4* kw4 = reinterpret_cast<const float4*>(key_w);
    #pragma unroll
    for (int i = 0; i < 8; i++) sw4[tid + i * 256] = kw4[tid + i * 256];
    if (tid < HH) sb[tid] = key_b[tid];

    // ---- span bounds, with int64-vs-int32 self-detection.
    // If begins/ends are int64 (values < 2^31, >= 0), the int32 view of `ends`
    // has all odd words == 0. If they are genuine int32, ends[i] >= 1 for all i
    // (widths >= 1), so odd words are nonzero. Deterministic, no false positive.
    if (tid == 0) {
        bool is64 = (ends32[1] == 0) && (ends32[3] == 0) &&
                    (ends32[5] == 0) && (ends32[7] == 0);
        int begin, end;
        if (is64) { begin = begins32[2 * blk]; end = ends32[2 * blk]; }
        else      { begin = begins32[blk];     end = ends32[blk];     }
        sspan[0] = begin; sspan[1] = end;
    }
    __syncthreads();
    const int begin = sspan[0];
    const int w     = sspan[1] - begin;   // 1..32

    // ---- phase 1: logits[t][h] = features[b,begin+t,:] . key_w[h,:] + key_b[h]
    // Warp wid owns rows [wid*4, wid*4+4); lanes stripe D in float4.
    // The 8 head key-vectors are loaded once per k-step and reused across 4 rows
    // -> FMA-bound, not smem-crossbar-bound.
    const int r0 = wid * 4;
    if (r0 < w) {
        const float4* f4[4];
        #pragma unroll
        for (int j = 0; j < 4; j++) {
            int r = r0 + j; if (r >= w) r = w - 1;   // clamp (result unused)
            f4[j] = reinterpret_cast<const float4*>(
                        features + ((size_t)b * TT + begin + r) * DD);
        }
        float acc[4][8];
        #pragma unroll
        for (int j = 0; j < 4; j++)
            #pragma unroll
            for (int h = 0; h < 8; h++) acc[j][h] = 0.f;

        for (int k = lane; k < NK; k += 32) {
            float4 kk[8];
            #pragma unroll
            for (int h = 0; h < 8; h++) kk[h] = sw4[h * NK + k];
            #pragma unroll
            for (int j = 0; j < 4; j++) {
                if (r0 + j < w) {                    // warp-uniform predicate
                    float4 a = f4[j][k];
                    #pragma unroll
                    for (int h = 0; h < 8; h++) {
                        acc[j][h] = fmaf(a.x, kk[h].x, acc[j][h]);
                        acc[j][h] = fmaf(a.y, kk[h].y, acc[j][h]);
                        acc[j][h] = fmaf(a.z, kk[h].z, acc[j][h]);
                        acc[j][h] = fmaf(a.w, kk[h].w, acc[j][h]);
                    }
                }
            }
        }
        #pragma unroll
        for (int j = 0; j < 4; j++) {
            if (r0 + j < w) {
                #pragma unroll
                for (int h = 0; h < 8; h++) {
                    float v = acc[j][h];
                    v += __shfl_xor_sync(0xffffffffu, v, 16);
                    v += __shfl_xor_sync(0xffffffffu, v, 8);
                    v += __shfl_xor_sync(0xffffffffu, v, 4);
                    v += __shfl_xor_sync(0xffffffffu, v, 2);
                    v += __shfl_xor_sync(0xffffffffu, v, 1);
                    if (lane == 0) slog[r0 + j][h] = v + sb[h];
                }
            }
        }
    }
    __syncthreads();

    // ---- phase 2: softmax over the span, per head (tiny: w <= 32)
    if (tid < HH) {
        float m = -3.0e38f;
        for (int t = 0; t < w; t++) m = fmaxf(m, slog[t][tid]);
        float sum = 0.f;
        for (int t = 0; t < w; t++) {
            float e = __expf(slog[t][tid] - m);
            slog[t][tid] = e;
            sum += e;
        }
        float inv = 1.f / sum;
        for (int t = 0; t < w; t++) slog[t][tid] *= inv;
    }
    __syncthreads();

    // ---- phase 3: out[b,s,h,dh] = sum_t weight[t][h] * features[b,begin+t,h*DH+dh]
    // Warp = head, lane covers 4 dh values; feature rows are L1-resident from phase 1.
    {
        const int h = wid;
        const float* vbase = features + ((size_t)b * TT + begin) * DD + h * DH + lane * 4;
        float4 o = make_float4(0.f, 0.f, 0.f, 0.f);
        for (int t = 0; t < w; t++) {
            float wt = slog[t][h];                    // LDS broadcast
            float4 f = *reinterpret_cast<const float4*>(vbase + (size_t)t * DD);
            o.x = fmaf(wt, f.x, o.x);
            o.y = fmaf(wt, f.y, o.y);
            o.z = fmaf(wt, f.z, o.z);
            o.w = fmaf(wt, f.w, o.w);
        }
        reinterpret_cast<float4*>(out + (size_t)blk * DD + h * DH)[lane] = o;
    }
}

extern "C" void kernel_launch(void* const* d_in, const int* in_sizes, int n_in,
                              void* d_out, int out_size)
{
    const float* features = (const float*)d_in[0];  // [B,T,D] f32
    const int*   begins   = (const int*)  d_in[1];  // [B,S] int32 or int64 (self-detected)
    const int*   ends     = (const int*)  d_in[2];  // [B,S] int32 or int64 (self-detected)
    const float* key_w    = (const float*)d_in[3];  // [H,D] f32
    const float* key_b    = (const float*)d_in[4];  // [H]   f32
    float*       out      = (float*)d_out;          // [B,S,D] f32

    pooler_kernel<<<BB * SS, 256>>>(features, begins, ends, key_w, key_b, out);
}

// round 7
// speedup vs baseline: 1.3126x; 1.3126x over previous
#include <cuda_runtime.h>
#include <cuda_bf16.h>

// Problem shapes (fixed by the dataset)
#define BB   8
#define TT   2048
#define DD   1024
#define HH   8
#define SS   128
#define DH   128      // D / H
#define MAXW 32       // max span width
#define NK   (DD/4)   // 256 float4 per row

// Scratch: logits for every token, [B*T, H] = 131072 floats = 512 KB
__device__ float g_logits[BB * TT * HH];

// ---------------------------------------------------------------------------
// Kernel 1: logits[row, h] = features[row, :] . key_w[h, :] + key_b[h]
// warp = row (8 rows/block), lanes stripe D in float4, keys served from L1.
// Grid = 16384 / 8 = 2048 blocks. Memory-streaming + FMA balanced.
// ---------------------------------------------------------------------------
__global__ __launch_bounds__(256)
void logits_kernel(const float* __restrict__ features,
                   const float* __restrict__ key_w,
                   const float* __restrict__ key_b)
{
    const int lane = threadIdx.x & 31;
    const int wid  = threadIdx.x >> 5;
    const int row  = blockIdx.x * 8 + wid;          // 0 .. 16383 exactly

    const float4* f4  = reinterpret_cast<const float4*>(features) + (size_t)row * NK;
    const float4* kw4 = reinterpret_cast<const float4*>(key_w);

    float acc[HH];
    #pragma unroll
    for (int h = 0; h < HH; h++) acc[h] = 0.f;

    #pragma unroll 2
    for (int k = lane; k < NK; k += 32) {
        float4 a = f4[k];
        #pragma unroll
        for (int h = 0; h < HH; h++) {
            float4 kk = kw4[h * NK + k];            // L1-resident (32 KB total)
            acc[h] = fmaf(a.x, kk.x, acc[h]);
            acc[h] = fmaf(a.y, kk.y, acc[h]);
            acc[h] = fmaf(a.z, kk.z, acc[h]);
            acc[h] = fmaf(a.w, kk.w, acc[h]);
        }
    }

    float myv = 0.f;
    #pragma unroll
    for (int h = 0; h < HH; h++) {
        float v = acc[h];
        v += __shfl_xor_sync(0xffffffffu, v, 16);
        v += __shfl_xor_sync(0xffffffffu, v, 8);
        v += __shfl_xor_sync(0xffffffffu, v, 4);
        v += __shfl_xor_sync(0xffffffffu, v, 2);
        v += __shfl_xor_sync(0xffffffffu, v, 1);
        if (lane == h) myv = v;                     // lane h keeps head h
    }
    if (lane < HH)
        g_logits[(size_t)row * HH + lane] = myv + key_b[lane];
}

// ---------------------------------------------------------------------------
// Kernel 2: per (b,s): span softmax over precomputed logits, then
// out[b,s,d] = sum_t weight[t, d/DH] * features[b, begin+t, d]
// Thread tid owns float4 chunk tid of D (head = tid>>5 -> weight is a warp
// broadcast). Whole grid (1024 blocks) resident in one wave.
// ---------------------------------------------------------------------------
__global__ __launch_bounds__(256)
void pool_kernel(const float* __restrict__ features,
                 const int*   __restrict__ begins32,
                 const int*   __restrict__ ends32,
                 float*       __restrict__ out)
{
    __shared__ float slog[MAXW][HH];
    __shared__ int   sspan[2];

    const int tid  = threadIdx.x;
    const int lane = tid & 31;
    const int wid  = tid >> 5;
    const int blk  = blockIdx.x;      // b*S + s
    const int b    = blk >> 7;

    // int64-vs-int32 self-detection (ends[i] >= 1 always, so odd words of a
    // genuine int32 buffer are nonzero; int64 high words are zero).
    if (tid == 0) {
        bool is64 = (ends32[1] == 0) && (ends32[3] == 0) &&
                    (ends32[5] == 0) && (ends32[7] == 0);
        int begin, end;
        if (is64) { begin = begins32[2 * blk]; end = ends32[2 * blk]; }
        else      { begin = begins32[blk];     end = ends32[blk];     }
        sspan[0] = begin; sspan[1] = end;
    }
    __syncthreads();
    const int begin = sspan[0];
    const int w     = sspan[1] - begin;              // 1..32

    // Load span logits into shared: tid covers (t, h) pairs, 8*w <= 256.
    if (tid < HH * w) {
        int t = tid >> 3, h = tid & 7;
        slog[t][h] = g_logits[((size_t)b * TT + begin + t) * HH + h];
    }
    __syncthreads();

    // Warp-parallel softmax: warp 0, lane = t, loop over heads.
    if (wid == 0) {
        #pragma unroll
        for (int h = 0; h < HH; h++) {
            float v = (lane < w) ? slog[lane][h] : -3.0e38f;
            float m = v;
            m = fmaxf(m, __shfl_xor_sync(0xffffffffu, m, 16));
            m = fmaxf(m, __shfl_xor_sync(0xffffffffu, m, 8));
            m = fmaxf(m, __shfl_xor_sync(0xffffffffu, m, 4));
            m = fmaxf(m, __shfl_xor_sync(0xffffffffu, m, 2));
            m = fmaxf(m, __shfl_xor_sync(0xffffffffu, m, 1));
            float e = (lane < w) ? __expf(v - m) : 0.f;
            float s = e;
            s += __shfl_xor_sync(0xffffffffu, s, 16);
            s += __shfl_xor_sync(0xffffffffu, s, 8);
            s += __shfl_xor_sync(0xffffffffu, s, 4);
            s += __shfl_xor_sync(0xffffffffu, s, 2);
            s += __shfl_xor_sync(0xffffffffu, s, 1);
            if (lane < w) slog[lane][h] = e * (1.f / s);
        }
    }
    __syncthreads();

    // Weighted sum over span rows. Row stride = NK float4.
    const int h = wid;                               // tid*4 / DH == tid>>5
    const float4* vb = reinterpret_cast<const float4*>(features)
                       + ((size_t)b * TT + begin) * NK + tid;
    float4 o = make_float4(0.f, 0.f, 0.f, 0.f);
    int t = 0;
    for (; t + 4 <= w; t += 4) {                     // unroll x4 for MLP
        float4 f0 = vb[(size_t)(t + 0) * NK];
        float4 f1 = vb[(size_t)(t + 1) * NK];
        float4 f2 = vb[(size_t)(t + 2) * NK];
        float4 f3 = vb[(size_t)(t + 3) * NK];
        float w0 = slog[t + 0][h], w1 = slog[t + 1][h];
        float w2 = slog[t + 2][h], w3 = slog[t + 3][h];
        o.x = fmaf(w0, f0.x, o.x); o.y = fmaf(w0, f0.y, o.y);
        o.z = fmaf(w0, f0.z, o.z); o.w = fmaf(w0, f0.w, o.w);
        o.x = fmaf(w1, f1.x, o.x); o.y = fmaf(w1, f1.y, o.y);
        o.z = fmaf(w1, f1.z, o.z); o.w = fmaf(w1, f1.w, o.w);
        o.x = fmaf(w2, f2.x, o.x); o.y = fmaf(w2, f2.y, o.y);
        o.z = fmaf(w2, f2.z, o.z); o.w = fmaf(w2, f2.w, o.w);
        o.x = fmaf(w3, f3.x, o.x); o.y = fmaf(w3, f3.y, o.y);
        o.z = fmaf(w3, f3.z, o.z); o.w = fmaf(w3, f3.w, o.w);
    }
    for (; t < w; t++) {
        float4 f = vb[(size_t)t * NK];
        float wt = slog[t][h];
        o.x = fmaf(wt, f.x, o.x); o.y = fmaf(wt, f.y, o.y);
        o.z = fmaf(wt, f.z, o.z); o.w = fmaf(wt, f.w, o.w);
    }
    reinterpret_cast<float4*>(out)[(size_t)blk * NK + tid] = o;
}

extern "C" void kernel_launch(void* const* d_in, const int* in_sizes, int n_in,
                              void* d_out, int out_size)
{
    const float* features = (const float*)d_in[0];  // [B,T,D] f32
    const int*   begins   = (const int*)  d_in[1];  // [B,S] int32/int64 (self-detected)
    const int*   ends     = (const int*)  d_in[2];
    const float* key_w    = (const float*)d_in[3];  // [H,D] f32
    const float* key_b    = (const float*)d_in[4];  // [H]   f32
    float*       out      = (float*)d_out;          // [B,S,D] f32

    logits_kernel<<<(BB * TT) / 8, 256>>>(features, key_w, key_b);
    pool_kernel<<<BB * SS, 256>>>(features, begins, ends, out);
}

// round 8
// speedup vs baseline: 1.3446x; 1.0244x over previous
#include <cuda_runtime.h>
#include <cuda_bf16.h>

// Problem shapes (fixed by the dataset)
#define BB   8
#define TT   2048
#define DD   1024
#define HH   8
#define SS   128
#define DH   128      // D / H
#define MAXW 32       // max span width
#define NK   (DD/4)   // 256 16-byte chunks per row

// Scratch: logits for every token, [B*T, H] = 131072 floats = 512 KB
__device__ float g_logits[BB * TT * HH];

// packed fp32x2 FMA (Blackwell; ptxas never emits it from C++)
#define FMA2(d, a, b, c) \
    asm("fma.rn.f32x2 %0, %1, %2, %3;" : "=l"(d) : "l"(a), "l"(b), "l"(c))

static __device__ __forceinline__ float pairsum(unsigned long long x) {
    float lo, hi;
    asm("mov.b64 {%0, %1}, %2;" : "=f"(lo), "=f"(hi) : "l"(x));
    return lo + hi;
}

// ---------------------------------------------------------------------------
// Kernel 1: logits[row, h] = features[row, :] . key_w[h, :] + key_b[h]
// 2 rows per warp (keys loaded once, reused across both rows), lanes stripe
// D in 16B chunks loaded as ulonglong2 = pre-packed f32x2 operands.
// Per k-iter/warp: 10 LDG (40 cyc LSU) vs 32 FFMA2 (64 cyc FMA) -> FMA floor
// halved vs scalar, kernel becomes DRAM-bound.
// ---------------------------------------------------------------------------
__global__ __launch_bounds__(128)
void logits_kernel(const float* __restrict__ features,
                   const float* __restrict__ key_w,
                   const float* __restrict__ key_b)
{
    const int lane = threadIdx.x & 31;
    const int wid  = threadIdx.x >> 5;
    const int row0 = blockIdx.x * 8 + wid * 2;       // 2 rows per warp

    const ulonglong2* f0 = reinterpret_cast<const ulonglong2*>(
                               features + (size_t)row0 * DD);
    const ulonglong2* f1 = reinterpret_cast<const ulonglong2*>(
                               features + (size_t)(row0 + 1) * DD);
    const ulonglong2* kw = reinterpret_cast<const ulonglong2*>(key_w);

    unsigned long long acc[2][HH][2];
    #pragma unroll
    for (int r = 0; r < 2; r++)
        #pragma unroll
        for (int h = 0; h < HH; h++) { acc[r][h][0] = 0ull; acc[r][h][1] = 0ull; }

    #pragma unroll 2
    for (int k = lane; k < NK; k += 32) {
        ulonglong2 a0 = f0[k];
        ulonglong2 a1 = f1[k];
        #pragma unroll
        for (int h = 0; h < HH; h++) {
            ulonglong2 kk = kw[h * NK + k];          // L1-resident (32 KB)
            FMA2(acc[0][h][0], a0.x, kk.x, acc[0][h][0]);
            FMA2(acc[0][h][1], a0.y, kk.y, acc[0][h][1]);
            FMA2(acc[1][h][0], a1.x, kk.x, acc[1][h][0]);
            FMA2(acc[1][h][1], a1.y, kk.y, acc[1][h][1]);
        }
    }

    #pragma unroll
    for (int r = 0; r < 2; r++) {
        float myv = 0.f;
        #pragma unroll
        for (int h = 0; h < HH; h++) {
            float v = pairsum(acc[r][h][0]) + pairsum(acc[r][h][1]);
            v += __shfl_xor_sync(0xffffffffu, v, 16);
            v += __shfl_xor_sync(0xffffffffu, v, 8);
            v += __shfl_xor_sync(0xffffffffu, v, 4);
            v += __shfl_xor_sync(0xffffffffu, v, 2);
            v += __shfl_xor_sync(0xffffffffu, v, 1);
            if (lane == h) myv = v;                  // lane h keeps head h
        }
        if (lane < HH)
            g_logits[(size_t)(row0 + r) * HH + lane] = myv + key_b[lane];
    }
}

// ---------------------------------------------------------------------------
// Kernel 2: per (b,s): span softmax over precomputed logits (warp h reduces
// head h in parallel), then out[b,s,d] = sum_t weight[t, d/DH] * feat[...].
// Thread tid owns 16B chunk tid of D; weight is an LDS warp-broadcast.
// ---------------------------------------------------------------------------
__global__ __launch_bounds__(256)
void pool_kernel(const float* __restrict__ features,
                 const int*   __restrict__ begins32,
                 const int*   __restrict__ ends32,
                 float*       __restrict__ out)
{
    __shared__ float slog[MAXW][HH];
    __shared__ int   sspan[2];

    const int tid  = threadIdx.x;
    const int lane = tid & 31;
    const int wid  = tid >> 5;
    const int blk  = blockIdx.x;      // b*S + s
    const int b    = blk >> 7;

    // int64-vs-int32 self-detection (ends[i] >= 1 always, so odd words of a
    // genuine int32 buffer are nonzero; int64 high words are zero).
    if (tid == 0) {
        bool is64 = (ends32[1] == 0) && (ends32[3] == 0) &&
                    (ends32[5] == 0) && (ends32[7] == 0);
        int begin, end;
        if (is64) { begin = begins32[2 * blk]; end = ends32[2 * blk]; }
        else      { begin = begins32[blk];     end = ends32[blk];     }
        sspan[0] = begin; sspan[1] = end;
    }
    __syncthreads();
    const int begin = sspan[0];
    const int w     = sspan[1] - begin;              // 1..32

    // Gather span logits into shared: tid covers (t, h) pairs, 8*w <= 256.
    if (tid < HH * w) {
        int t = tid >> 3, h = tid & 7;
        slog[t][h] = g_logits[((size_t)b * TT + begin + t) * HH + h];
    }
    __syncthreads();

    // Parallel softmax: warp h reduces head h (lane = t).
    {
        const int h = wid;
        float v = (lane < w) ? slog[lane][h] : -3.0e38f;
        float m = v;
        m = fmaxf(m, __shfl_xor_sync(0xffffffffu, m, 16));
        m = fmaxf(m, __shfl_xor_sync(0xffffffffu, m, 8));
        m = fmaxf(m, __shfl_xor_sync(0xffffffffu, m, 4));
        m = fmaxf(m, __shfl_xor_sync(0xffffffffu, m, 2));
        m = fmaxf(m, __shfl_xor_sync(0xffffffffu, m, 1));
        float e = (lane < w) ? __expf(v - m) : 0.f;
        float s = e;
        s += __shfl_xor_sync(0xffffffffu, s, 16);
        s += __shfl_xor_sync(0xffffffffu, s, 8);
        s += __shfl_xor_sync(0xffffffffu, s, 4);
        s += __shfl_xor_sync(0xffffffffu, s, 2);
        s += __shfl_xor_sync(0xffffffffu, s, 1);
        if (lane < w) slog[lane][h] = e * (1.f / s);
    }
    __syncthreads();

    // Weighted sum over span rows, unrolled x8 for load MLP.
    const int h = wid;                               // (tid*4) / DH == tid>>5
    const float4* vb = reinterpret_cast<const float4*>(features)
                       + ((size_t)b * TT + begin) * NK + tid;
    float4 o = make_float4(0.f, 0.f, 0.f, 0.f);
    int t = 0;
    for (; t + 8 <= w; t += 8) {
        float4 f[8];
        float  wt[8];
        #pragma unroll
        for (int j = 0; j < 8; j++) f[j]  = vb[(size_t)(t + j) * NK];
        #pragma unroll
        for (int j = 0; j < 8; j++) wt[j] = slog[t + j][h];
        #pragma unroll
        for (int j = 0; j < 8; j++) {
            o.x = fmaf(wt[j], f[j].x, o.x);
            o.y = fmaf(wt[j], f[j].y, o.y);
            o.z = fmaf(wt[j], f[j].z, o.z);
            o.w = fmaf(wt[j], f[j].w, o.w);
        }
    }
    for (; t < w; t++) {
        float4 f = vb[(size_t)t * NK];
        float wt = slog[t][h];
        o.x = fmaf(wt, f.x, o.x);
        o.y = fmaf(wt, f.y, o.y);
        o.z = fmaf(wt, f.z, o.z);
        o.w = fmaf(wt, f.w, o.w);
    }
    reinterpret_cast<float4*>(out)[(size_t)blk * NK + tid] = o;
}

extern "C" void kernel_launch(void* const* d_in, const int* in_sizes, int n_in,
                              void* d_out, int out_size)
{
    const float* features = (const float*)d_in[0];  // [B,T,D] f32
    const int*   begins   = (const int*)  d_in[1];  // [B,S] int32/int64 (self-detected)
    const int*   ends     = (const int*)  d_in[2];
    const float* key_w    = (const float*)d_in[3];  // [H,D] f32
    const float* key_b    = (const float*)d_in[4];  // [H]   f32
    float*       out      = (float*)d_out;          // [B,S,D] f32

    logits_kernel<<<(BB * TT) / 8, 128>>>(features, key_w, key_b);
    pool_kernel<<<BB * SS, 256>>>(features, begins, ends, out);
}

// round 9
// speedup vs baseline: 1.5719x; 1.1690x over previous
#include <cuda_runtime.h>
#include <cuda_bf16.h>

// Problem shapes (fixed by the dataset)
#define BB   8
#define TT   2048
#define DD   1024
#define HH   8
#define SS   128
#define DH   128      // D / H
#define MAXW 32       // max span width
#define NK   (DD/4)   // 256 16-byte chunks per row
#define RPB  16       // rows per logits block
#define GRP  8        // groups of 2 rows

// Scratch: logits for every token, [B*T, H] = 131072 floats = 512 KB
__device__ float g_logits[BB * TT * HH];

// packed fp32x2 FMA (Blackwell; ptxas never emits it from C++)
#define FMA2(d, a, b, c) \
    asm("fma.rn.f32x2 %0, %1, %2, %3;" : "=l"(d) : "l"(a), "l"(b), "l"(c))

static __device__ __forceinline__ float pairsum(unsigned long long x) {
    float lo, hi;
    asm("mov.b64 {%0, %1}, %2;" : "=f"(lo), "=f"(hi) : "l"(x));
    return lo + hi;
}

// ---------------------------------------------------------------------------
// Kernel 1: logits[row, h] = features[row, :] . key_w[h, :] + key_b[h]
// Thread tid owns 16B chunk tid of D; ALL 8 heads' keys for that chunk are
// register-resident (loaded once per block). Rows processed 2 at a time with
// prefetch -> exactly 1 feature LDG.128 per thread per row, zero steady-state
// key traffic. Cross-lane combine: 31-shfl multi-value butterfly.
// ---------------------------------------------------------------------------
__global__ __launch_bounds__(256)
void logits_kernel(const float* __restrict__ features,
                   const float* __restrict__ key_w,
                   const float* __restrict__ key_b)
{
    __shared__ float partial[GRP][8][16];   // [group][warp][val], 4 KB

    const int tid  = threadIdx.x;
    const int lane = tid & 31;
    const int wid  = tid >> 5;
    const int rowbase = blockIdx.x * RPB;

    // keys for this chunk, all heads, in registers (32 regs)
    const ulonglong2* kw = reinterpret_cast<const ulonglong2*>(key_w);
    ulonglong2 kk[HH];
    #pragma unroll
    for (int h = 0; h < HH; h++) kk[h] = kw[h * NK + tid];

    const ulonglong2* fb = reinterpret_cast<const ulonglong2*>(features);

    // prefetch group 0
    ulonglong2 f0 = fb[(size_t)(rowbase + 0) * NK + tid];
    ulonglong2 f1 = fb[(size_t)(rowbase + 1) * NK + tid];

    #pragma unroll
    for (int g = 0; g < GRP; g++) {
        ulonglong2 a0 = f0, a1 = f1;
        if (g + 1 < GRP) {                 // prefetch next group during compute
            f0 = fb[(size_t)(rowbase + 2 * g + 2) * NK + tid];
            f1 = fb[(size_t)(rowbase + 2 * g + 3) * NK + tid];
        }

        unsigned long long acc[HH][2];
        #pragma unroll
        for (int h = 0; h < HH; h++) { acc[h][0] = 0ull; acc[h][1] = 0ull; }
        #pragma unroll
        for (int h = 0; h < HH; h++) {
            FMA2(acc[h][0], a0.x, kk[h].x, acc[h][0]);
            FMA2(acc[h][0], a0.y, kk[h].y, acc[h][0]);
            FMA2(acc[h][1], a1.x, kk[h].x, acc[h][1]);
            FMA2(acc[h][1], a1.y, kk[h].y, acc[h][1]);
        }

        // v[idx], idx = h*2 + r
        float v[16];
        #pragma unroll
        for (int h = 0; h < HH; h++) {
            v[h * 2 + 0] = pairsum(acc[h][0]);
            v[h * 2 + 1] = pairsum(acc[h][1]);
        }

        // stage A: fold lanes 16..31 onto 0..15 (all 16 values)
        #pragma unroll
        for (int i = 0; i < 16; i++)
            v[i] += __shfl_xor_sync(0xffffffffu, v[i], 16);

        // value-halving butterfly: masks 8,4,2,1; lane l ends with total of v[l&15]
        #pragma unroll
        for (int m = 8; m >= 1; m >>= 1) {
            const int nvh = m;                    // nv/2 = 8,4,2,1
            bool up = (lane & m) != 0;
            #pragma unroll
            for (int i = 0; i < 8; i++) {
                if (i < nvh) {
                    float send = up ? v[i] : v[i + nvh];
                    float recv = __shfl_xor_sync(0xffffffffu, send, m);
                    v[i] = (up ? v[i + nvh] : v[i]) + recv;
                }
            }
        }
        if (lane < 16) partial[g][wid][lane] = v[0];
    }
    __syncthreads();

    // final combine: threads 0..127, one (group, idx) each
    if (tid < GRP * 16) {
        const int g   = tid >> 4;
        const int idx = tid & 15;
        const int h   = idx >> 1;
        const int r   = idx & 1;
        float s = 0.f;
        #pragma unroll
        for (int wq = 0; wq < 8; wq++) s += partial[g][wq][idx];
        g_logits[(size_t)(rowbase + g * 2 + r) * HH + h] = s + key_b[h];
    }
}

// ---------------------------------------------------------------------------
// Kernel 2 (barrier-free): per (b,s): warp h computes head-h span softmax from
// g_logits (lane = t, weight kept in a register), then streams the weighted
// sum with shfl-broadcast weights. Thread tid owns 16B chunk tid of D.
// ---------------------------------------------------------------------------
__global__ __launch_bounds__(256)
void pool_kernel(const float* __restrict__ features,
                 const int*   __restrict__ begins32,
                 const int*   __restrict__ ends32,
                 float*       __restrict__ out)
{
    const int tid  = threadIdx.x;
    const int lane = tid & 31;
    const int wid  = tid >> 5;
    const int blk  = blockIdx.x;      // b*S + s
    const int b    = blk >> 7;

    // span bounds (uniform loads, no barrier). int64-vs-int32 self-detection:
    // genuine int32 ends are >=1 everywhere; int64 high words are zero.
    bool is64 = (ends32[1] == 0) && (ends32[3] == 0) &&
                (ends32[5] == 0) && (ends32[7] == 0);
    int begin, end;
    if (is64) { begin = begins32[2 * blk]; end = ends32[2 * blk]; }
    else      { begin = begins32[blk];     end = ends32[blk];     }
    const int w = end - begin;                       // 1..32

    // per-warp softmax for head h = wid; lane = t
    const int h = wid;
    float v = (lane < w)
            ? g_logits[((size_t)b * TT + begin + lane) * HH + h]
            : -3.0e38f;
    float m = v;
    m = fmaxf(m, __shfl_xor_sync(0xffffffffu, m, 16));
    m = fmaxf(m, __shfl_xor_sync(0xffffffffu, m, 8));
    m = fmaxf(m, __shfl_xor_sync(0xffffffffu, m, 4));
    m = fmaxf(m, __shfl_xor_sync(0xffffffffu, m, 2));
    m = fmaxf(m, __shfl_xor_sync(0xffffffffu, m, 1));
    float e = (lane < w) ? __expf(v - m) : 0.f;
    float s = e;
    s += __shfl_xor_sync(0xffffffffu, s, 16);
    s += __shfl_xor_sync(0xffffffffu, s, 8);
    s += __shfl_xor_sync(0xffffffffu, s, 4);
    s += __shfl_xor_sync(0xffffffffu, s, 2);
    s += __shfl_xor_sync(0xffffffffu, s, 1);
    const float wval = e * (1.f / s);                // lane t's weight, head h

    // weighted sum over span rows; weights broadcast via shfl (no smem/barrier)
    const float4* vb = reinterpret_cast<const float4*>(features)
                       + ((size_t)b * TT + begin) * NK + tid;
    float4 o = make_float4(0.f, 0.f, 0.f, 0.f);
    int t = 0;
    for (; t + 8 <= w; t += 8) {
        float4 f[8];
        #pragma unroll
        for (int j = 0; j < 8; j++) f[j] = vb[(size_t)(t + j) * NK];
        #pragma unroll
        for (int j = 0; j < 8; j++) {
            float wt = __shfl_sync(0xffffffffu, wval, t + j);
            o.x = fmaf(wt, f[j].x, o.x);
            o.y = fmaf(wt, f[j].y, o.y);
            o.z = fmaf(wt, f[j].z, o.z);
            o.w = fmaf(wt, f[j].w, o.w);
        }
    }
    for (; t < w; t++) {
        float4 f = vb[(size_t)t * NK];
        float wt = __shfl_sync(0xffffffffu, wval, t);
        o.x = fmaf(wt, f.x, o.x);
        o.y = fmaf(wt, f.y, o.y);
        o.z = fmaf(wt, f.z, o.z);
        o.w = fmaf(wt, f.w, o.w);
    }
    reinterpret_cast<float4*>(out)[(size_t)blk * NK + tid] = o;
}

extern "C" void kernel_launch(void* const* d_in, const int* in_sizes, int n_in,
                              void* d_out, int out_size)
{
    const float* features = (const float*)d_in[0];  // [B,T,D] f32
    const int*   begins   = (const int*)  d_in[1];  // [B,S] int32/int64 (self-detected)
    const int*   ends     = (const int*)  d_in[2];
    const float* key_w    = (const float*)d_in[3];  // [H,D] f32
    const float* key_b    = (const float*)d_in[4];  // [H]   f32
    float*       out      = (float*)d_out;          // [B,S,D] f32

    logits_kernel<<<(BB * TT) / RPB, 256>>>(features, key_w, key_b);
    pool_kernel<<<BB * SS, 256>>>(features, begins, ends, out);
}

// round 12
// speedup vs baseline: 1.7191x; 1.0936x over previous
#include <cuda_runtime.h>
#include <cuda_bf16.h>
#include <cstdint>

// Problem shapes (fixed by the dataset)
#define BB   8
#define TT   2048
#define DD   1024
#define HH   8
#define SS   128
#define DH   128      // D / H
#define MAXW 32       // max span width
#define NK   (DD/4)   // 256 16-byte chunks per row
#define RPB  32       // rows per logits block
#define RG   4        // rows per group
#define NGRP (RPB/RG) // 8
#define RING 2        // cp.async ring depth (groups)

// Scratch: logits for every token, [B*T, H] = 512 KB; decoded spans 8 KB
__device__ float g_logits[BB * TT * HH];
__device__ int2  g_span[BB * SS];

// packed fp32x2 FMA (Blackwell; ptxas never emits it from C++)
#define FMA2(d, a, b, c) \
    asm("fma.rn.f32x2 %0, %1, %2, %3;" : "=l"(d) : "l"(a), "l"(b), "l"(c))

static __device__ __forceinline__ float pairsum(unsigned long long x) {
    float lo, hi;
    asm("mov.b64 {%0, %1}, %2;" : "=f"(lo), "=f"(hi) : "l"(x));
    return lo + hi;
}

// ---------------------------------------------------------------------------
// Kernel 1: logits[row, h] = features[row, :] . key_w[h, :] + key_b[h]
// Thread tid owns 16B chunk tid of D; all 8 heads' keys register-resident.
// Feature rows staged through a cp.async smem ring (4 rows/group, 2 groups
// in flight). Each thread copies and consumes only its own chunk -> no
// barrier inside the pipeline. Reduction: ONE 31-shfl value-halving
// butterfly per 4 rows. Blocks 0..3 also decode span bounds into g_span.
//
// wait_group discipline: pending set at iter g is {g, g+1}, so wait_group 1
// drains group g -- EXCEPT the last iter, where only one group is pending and
// wait_group 1 would be a no-op. The last iter must use wait_group 0.
// ---------------------------------------------------------------------------
__global__ __launch_bounds__(256, 2)
void logits_kernel(const float* __restrict__ features,
                   const float* __restrict__ key_w,
                   const float* __restrict__ key_b,
                   const int*   __restrict__ begins32,
                   const int*   __restrict__ ends32)
{
    __shared__ ulonglong2 ring[RING][RG][256];   // 32 KB
    __shared__ float partial[NGRP][8][32];       // 8 KB

    const int tid     = threadIdx.x;
    const int lane    = tid & 31;
    const int wid     = tid >> 5;
    const int rowbase = blockIdx.x * RPB;

    // ---- side task: decode span bounds once for the whole problem.
    // int64-vs-int32 self-detection: genuine int32 ends are >=1 everywhere;
    // int64 high words are zero.
    if (blockIdx.x < 4) {
        const int sp = blockIdx.x * 256 + tid;   // 4*256 = 1024 spans
        bool is64 = (ends32[1] == 0) && (ends32[3] == 0) &&
                    (ends32[5] == 0) && (ends32[7] == 0);
        int begin, end;
        if (is64) { begin = begins32[2 * sp]; end = ends32[2 * sp]; }
        else      { begin = begins32[sp];     end = ends32[sp];     }
        g_span[sp] = make_int2(begin, end - begin);
    }

    // ---- keys for this chunk, all heads, in registers (32 regs)
    const ulonglong2* kw = reinterpret_cast<const ulonglong2*>(key_w);
    ulonglong2 kk[HH];
    #pragma unroll
    for (int h = 0; h < HH; h++) kk[h] = kw[h * NK + tid];

    const char* fbase = reinterpret_cast<const char*>(features)
                        + (size_t)rowbase * (DD * 4) + (size_t)tid * 16;

    // ---- cp.async pipeline
    #define ISSUE_GROUP(g)                                                      \
    do {                                                                        \
        unsigned int _dst = (unsigned int)__cvta_generic_to_shared(             \
                            &ring[(g) % RING][0][tid]);                         \
        _Pragma("unroll")                                                       \
        for (int _r = 0; _r < RG; _r++) {                                       \
            const char* _src = fbase + (size_t)((g) * RG + _r) * (DD * 4);      \
            asm volatile("cp.async.cg.shared.global [%0], [%1], 16;"            \
                         :: "r"(_dst + _r * (256 * 16)), "l"(_src) : "memory"); \
        }                                                                       \
        asm volatile("cp.async.commit_group;" ::: "memory");                    \
    } while (0)

    ISSUE_GROUP(0);
    ISSUE_GROUP(1);

    #pragma unroll
    for (int g = 0; g < NGRP; g++) {
        // drain group g: at g == NGRP-1 only one group is pending, so
        // wait_group 1 would NOT wait -- must use wait_group 0 there.
        if (g == NGRP - 1)
            asm volatile("cp.async.wait_group 0;" ::: "memory");
        else
            asm volatile("cp.async.wait_group 1;" ::: "memory");
        const int buf = g % RING;

        ulonglong2 a[RG];
        #pragma unroll
        for (int r = 0; r < RG; r++) a[r] = ring[buf][r][tid];

        // refill this slot (LDS above already issued; async data lands ~600cyc later)
        if (g + RING < NGRP) ISSUE_GROUP(g + RING);

        unsigned long long acc[HH][RG];
        #pragma unroll
        for (int h = 0; h < HH; h++)
            #pragma unroll
            for (int r = 0; r < RG; r++) acc[h][r] = 0ull;

        #pragma unroll
        for (int h = 0; h < HH; h++) {
            #pragma unroll
            for (int r = 0; r < RG; r++) {
                FMA2(acc[h][r], a[r].x, kk[h].x, acc[h][r]);
                FMA2(acc[h][r], a[r].y, kk[h].y, acc[h][r]);
            }
        }

        // v[idx], idx = h*4 + r  (32 values across 32 lanes)
        float v[32];
        #pragma unroll
        for (int h = 0; h < HH; h++)
            #pragma unroll
            for (int r = 0; r < RG; r++)
                v[h * 4 + r] = pairsum(acc[h][r]);

        // value-halving butterfly: after masks 16,8,4,2,1, lane l holds the
        // warp-total of v_orig[l].
        #pragma unroll
        for (int m = 16; m >= 1; m >>= 1) {
            const bool up = (lane & m) != 0;
            #pragma unroll
            for (int i = 0; i < 16; i++) {
                if (i < m) {
                    float send = up ? v[i] : v[i + m];
                    float recv = __shfl_xor_sync(0xffffffffu, send, m);
                    v[i] = (up ? v[i + m] : v[i]) + recv;
                }
            }
        }
        partial[g][wid][lane] = v[0];
    }
    __syncthreads();

    // final combine: 256 threads, one (group, idx) each; sum the 8 warps
    {
        const int g   = tid >> 5;
        const int idx = tid & 31;
        const int h   = idx >> 2;
        const int r   = idx & 3;
        float s = 0.f;
        #pragma unroll
        for (int wq = 0; wq < 8; wq++) s += partial[g][wq][idx];
        g_logits[(size_t)(rowbase + g * RG + r) * HH + h] = s + key_b[h];
    }
    #undef ISSUE_GROUP
}

// ---------------------------------------------------------------------------
// Kernel 2 (barrier-free, prefetch-first): per (b,s), span from g_span (one
// load). First 8 feature rows are issued BEFORE the softmax so its latency is
// covered by in-flight loads; then double-buffered batches of 4 keep loads
// continuous. Weights for t >= w are exactly 0, so clamped rows contribute 0.
// ---------------------------------------------------------------------------
__global__ __launch_bounds__(256)
void pool_kernel(const float* __restrict__ features,
                 float*       __restrict__ out)
{
    const int tid  = threadIdx.x;
    const int lane = tid & 31;
    const int wid  = tid >> 5;
    const int blk  = blockIdx.x;      // b*S + s
    const int b    = blk >> 7;

    const int2 se   = g_span[blk];
    const int begin = se.x;
    const int w     = se.y;                          // 1..32
    const int wm1   = w - 1;

    const float4* vb = reinterpret_cast<const float4*>(features)
                       + ((size_t)b * TT + begin) * NK + tid;

    // issue first two batches before the softmax
    float4 fA[4], fB[4];
    #pragma unroll
    for (int j = 0; j < 4; j++) fA[j] = vb[(size_t)min(j,     wm1) * NK];
    #pragma unroll
    for (int j = 0; j < 4; j++) fB[j] = vb[(size_t)min(4 + j, wm1) * NK];

    // per-warp softmax for head h = wid; lane = t (overlaps in-flight loads)
    const int h = wid;
    float v = (lane < w)
            ? g_logits[((size_t)b * TT + begin + lane) * HH + h]
            : -3.0e38f;
    float m = v;
    m = fmaxf(m, __shfl_xor_sync(0xffffffffu, m, 16));
    m = fmaxf(m, __shfl_xor_sync(0xffffffffu, m, 8));
    m = fmaxf(m, __shfl_xor_sync(0xffffffffu, m, 4));
    m = fmaxf(m, __shfl_xor_sync(0xffffffffu, m, 2));
    m = fmaxf(m, __shfl_xor_sync(0xffffffffu, m, 1));
    float e = (lane < w) ? __expf(v - m) : 0.f;
    float s = e;
    s += __shfl_xor_sync(0xffffffffu, s, 16);
    s += __shfl_xor_sync(0xffffffffu, s, 8);
    s += __shfl_xor_sync(0xffffffffu, s, 4);
    s += __shfl_xor_sync(0xffffffffu, s, 2);
    s += __shfl_xor_sync(0xffffffffu, s, 1);
    const float wval = e * (1.f / s);                // 0 for lanes >= w

    // double-buffered weighted sum; shfl-broadcast weights (lane index static)
    float4 o = make_float4(0.f, 0.f, 0.f, 0.f);
    const int nb = (w + 3) >> 2;                     // 1..8 batches of 4
    #pragma unroll
    for (int p = 0; p < 8; p++) {
        if (p < nb) {
            if ((p & 1) == 0) {
                #pragma unroll
                for (int j = 0; j < 4; j++) {
                    float wt = __shfl_sync(0xffffffffu, wval, p * 4 + j);
                    o.x = fmaf(wt, fA[j].x, o.x);
                    o.y = fmaf(wt, fA[j].y, o.y);
                    o.z = fmaf(wt, fA[j].z, o.z);
                    o.w = fmaf(wt, fA[j].w, o.w);
                }
                if (p + 2 < nb) {
                    #pragma unroll
                    for (int j = 0; j < 4; j++)
                        fA[j] = vb[(size_t)min(p * 4 + 8 + j, wm1) * NK];
                }
            } else {
                #pragma unroll
                for (int j = 0; j < 4; j++) {
                    float wt = __shfl_sync(0xffffffffu, wval, p * 4 + j);
                    o.x = fmaf(wt, fB[j].x, o.x);
                    o.y = fmaf(wt, fB[j].y, o.y);
                    o.z = fmaf(wt, fB[j].z, o.z);
                    o.w = fmaf(wt, fB[j].w, o.w);
                }
                if (p + 2 < nb) {
                    #pragma unroll
                    for (int j = 0; j < 4; j++)
                        fB[j] = vb[(size_t)min(p * 4 + 8 + j, wm1) * NK];
                }
            }
        }
    }
    reinterpret_cast<float4*>(out)[(size_t)blk * NK + tid] = o;
}

extern "C" void kernel_launch(void* const* d_in, const int* in_sizes, int n_in,
                              void* d_out, int out_size)
{
    const float* features = (const float*)d_in[0];  // [B,T,D] f32
    const int*   begins   = (const int*)  d_in[1];  // [B,S] int32/int64 (self-detected)
    const int*   ends     = (const int*)  d_in[2];
    const float* key_w    = (const float*)d_in[3];  // [H,D] f32
    const float* key_b    = (const float*)d_in[4];  // [H]   f32
    float*       out      = (float*)d_out;          // [B,S,D] f32

    logits_kernel<<<(BB * TT) / RPB, 256>>>(features, key_w, key_b, begins, ends);
    pool_kernel<<<BB * SS, 256>>>(features, out);
}